// round 14
// baseline (speedup 1.0000x reference)
#include <cuda_runtime.h>
#include <cuda_fp16.h>
#include <cstdint>

#define NPTS 16384
#define DIM  64
#define MB   32                  // rows per CTA
#define NBT  256                 // cols per tile
#define NT   512                 // threads (16 warps)
#define NCHUNK 8
#define COLS_PER_CTA (NPTS / NCHUNK)   // 2048
#define TILES (COLS_PER_CTA / NBT)     // 8

__device__ float g_sq[NPTS];
__device__ unsigned long long g_key[NPTS];
__device__ uint4 g_bf4[262144];          // 4MB fragment-major fp16 2-plane X (A and B)

// ---------------- helpers ----------------
#define MMA16(c, a0, a1, a2, a3, b0, b1) \
    asm volatile("mma.sync.aligned.m16n8k16.row.col.f32.f16.f16.f32 " \
        "{%0,%1,%2,%3},{%4,%5,%6,%7},{%8,%9},{%0,%1,%2,%3};" \
        : "+f"((c)[0]), "+f"((c)[1]), "+f"((c)[2]), "+f"((c)[3]) \
        : "r"(a0), "r"(a1), "r"(a2), "r"(a3), "r"(b0), "r"(b1))

__device__ __forceinline__ uint32_t pack_plane(float2 v, int p) {
    __half h0x = __float2half_rn(v.x);
    __half h0y = __float2half_rn(v.y);
    __half lx, ly;
    if (p == 0) { lx = h0x; ly = h0y; }
    else {
        lx = __float2half_rn(v.x - __half2float(h0x));
        ly = __float2half_rn(v.y - __half2float(h0y));
    }
    return (uint32_t)__half_as_ushort(lx) | ((uint32_t)__half_as_ushort(ly) << 16);
}

// ---------------- small kernels ----------------
__global__ void sq_kernel(const float* __restrict__ X) {
    int warp = (blockIdx.x * blockDim.x + threadIdx.x) >> 5;
    int lane = threadIdx.x & 31;
    if (warp >= NPTS) return;
    const float* row = X + (size_t)warp * DIM;
    float a = row[lane], b = row[lane + 32];
    float s = a * a + b * b;
    #pragma unroll
    for (int o = 16; o; o >>= 1) s += __shfl_xor_sync(0xffffffffu, s, o);
    if (lane == 0) g_sq[warp] = s;
}

// fragment-major fp16 planes: uint4 index = (((tile*4+s)*2+p)*8+npair)*32+lane
__global__ void prep_b(const float* __restrict__ X) {
    int gid = blockIdx.x * blockDim.x + threadIdx.x;   // 0..262143
    int lane = gid & 31;
    int r1 = gid >> 5;
    int npair = r1 & 7;
    int r2 = r1 >> 3;
    int p = r2 & 1;
    int r3 = r2 >> 1;
    int s = r3 & 3;
    int tile = r3 >> 2;
    int lg = lane >> 2, lt = lane & 3;
    int j0 = tile * 128 + npair * 16 + lg;
    int j1 = j0 + 8;
    int kb = s * 16 + 2 * lt;
    float2 e00 = *(const float2*)(X + (size_t)j0 * DIM + kb);
    float2 e01 = *(const float2*)(X + (size_t)j0 * DIM + kb + 8);
    float2 e10 = *(const float2*)(X + (size_t)j1 * DIM + kb);
    float2 e11 = *(const float2*)(X + (size_t)j1 * DIM + kb + 8);
    uint4 o;
    o.x = pack_plane(e00, p);
    o.y = pack_plane(e01, p);
    o.z = pack_plane(e10, p);
    o.w = pack_plane(e11, p);
    g_bf4[gid] = o;
}

__global__ void init_kernel() {
    g_key[blockIdx.x * blockDim.x + threadIdx.x] = 0xFFFFFFFFFFFFFFFFull;
}

__global__ void final_kernel(float* __restrict__ out) {
    int row = blockIdx.x * blockDim.x + threadIdx.x;
    unsigned idx = (unsigned)(g_key[row] & 0xFFFFFFFFu);
    out[(size_t)row * NPTS + row] = 1.0f;
    out[(size_t)row * NPTS + idx] = 1.0f;
}

// ---------------- main kernel: A in regs (32 rows), warp tile 32x16 ----------------
__global__ void __launch_bounds__(NT, 1)
knn_kernel(float* __restrict__ out) {
    __shared__ unsigned long long skey[MB][16];

    const int tid  = threadIdx.x;
    const int lane = tid & 31;
    const int cg   = tid >> 5;          // 0..15 -> 16-col group
    const int lg   = lane >> 2;         // 0..7
    const int lt   = lane & 3;          // 0..3
    const int row0 = blockIdx.x * MB;
    const int col0 = blockIdx.y * COLS_PER_CTA;
    const int wcol = (cg >> 3) * 128 + (cg & 7) * 16;   // warp col offset in tile

    // ---- A fragments: all 32 CTA rows resident in registers ----
    uint4 a[2][2][4];                    // [mf][plane][stage]
    #pragma unroll
    for (int mf = 0; mf < 2; mf++) {
        const int rbA = blockIdx.x * 2 + mf;
        const int tA = rbA >> 3, npA = rbA & 7;
        #pragma unroll
        for (int s = 0; s < 4; s++)
            #pragma unroll
            for (int p = 0; p < 2; p++)
                a[mf][p][s] = g_bf4[((((tA * 4 + s) * 2) + p) * 8 + npA) * 32 + lane];
    }

    // B base pointer: one npair per warp; all mainloop LDG immediate offsets
    const uint4* bp = g_bf4
        + (size_t)(blockIdx.y * 16 + (cg >> 3)) * 2048
        + (cg & 7) * 32 + lane;

    float mn[4];
    int   mi[4];
    #pragma unroll
    for (int q = 0; q < 4; q++) { mn[q] = 3.402823466e38f; mi[q] = 0; }

    // prologue: prefetch stages 0,1 of tile 0 (2 uint4 per stage)
    uint4 Bb[2][2];                      // [buf][plane]
    #pragma unroll
    for (int p = 0; p < 2; p++) {
        Bb[0][p] = bp[0 * 512 + p * 256];
        Bb[1][p] = bp[1 * 512 + p * 256];
    }

    for (int t = 0; t < TILES; t++) {
        const int cb = col0 + t * NBT;

        // prefetch sq-norms for this tile's epilogue
        float2 sb[2];
        #pragma unroll
        for (int nf = 0; nf < 2; nf++)
            sb[nf] = __ldg((const float2*)&g_sq[cb + wcol + nf * 8 + 2 * lt]);

        float acc[2][2][4];
        #pragma unroll
        for (int mf = 0; mf < 2; mf++)
            #pragma unroll
            for (int nf = 0; nf < 2; nf++)
                #pragma unroll
                for (int r = 0; r < 4; r++) acc[mf][nf][r] = 0.f;

        #pragma unroll
        for (int s = 0; s < 4; s++) {
            const int cur = s & 1;
            // 12 MMAs: h0h0, h0h1, h1h0 (h1h1 ~2^-22 dropped)
            #pragma unroll
            for (int mf = 0; mf < 2; mf++)
                #pragma unroll
                for (int nf = 0; nf < 2; nf++) {
                    const uint4& B = Bb[cur][0];
                    MMA16(acc[mf][nf], a[mf][0][s].x, a[mf][0][s].z, a[mf][0][s].y, a[mf][0][s].w,
                          nf ? B.z : B.x, nf ? B.w : B.y);
                }
            #pragma unroll
            for (int mf = 0; mf < 2; mf++)
                #pragma unroll
                for (int nf = 0; nf < 2; nf++) {
                    const uint4& B = Bb[cur][1];
                    MMA16(acc[mf][nf], a[mf][0][s].x, a[mf][0][s].z, a[mf][0][s].y, a[mf][0][s].w,
                          nf ? B.z : B.x, nf ? B.w : B.y);
                }
            #pragma unroll
            for (int mf = 0; mf < 2; mf++)
                #pragma unroll
                for (int nf = 0; nf < 2; nf++) {
                    const uint4& B = Bb[cur][0];
                    MMA16(acc[mf][nf], a[mf][1][s].x, a[mf][1][s].z, a[mf][1][s].y, a[mf][1][s].w,
                          nf ? B.z : B.x, nf ? B.w : B.y);
                }
            // depth-2 prefetch ring (WAR-safe: MMA reads above precede writes)
            if (s < 2) {
                #pragma unroll
                for (int p = 0; p < 2; p++)
                    Bb[cur][p] = bp[(s + 2) * 512 + p * 256];
            } else if (t + 1 < TILES) {
                #pragma unroll
                for (int p = 0; p < 2; p++)
                    Bb[cur][p] = bp[4096 + (s - 2) * 512 + p * 256];
            }
        }
        bp += 4096;

        // ---- epilogue: argmin of (sb - 2*dot); self excluded ----
        #pragma unroll
        for (int mf = 0; mf < 2; mf++) {
            const int ig = row0 + mf * 16 + lg;    // +8 for h=1 slots
            #pragma unroll
            for (int nf = 0; nf < 2; nf++) {
                const int lc = wcol + nf * 8 + 2 * lt;
                const int j0 = cb + lc, j1 = j0 + 1;
                float v;
                v = fmaf(-2.f, acc[mf][nf][0], sb[nf].x);
                if (j0 != ig && v < mn[mf * 2]) { mn[mf * 2] = v; mi[mf * 2] = j0; }
                v = fmaf(-2.f, acc[mf][nf][1], sb[nf].y);
                if (j1 != ig && v < mn[mf * 2]) { mn[mf * 2] = v; mi[mf * 2] = j1; }
                v = fmaf(-2.f, acc[mf][nf][2], sb[nf].x);
                if (j0 != ig + 8 && v < mn[mf * 2 + 1]) { mn[mf * 2 + 1] = v; mi[mf * 2 + 1] = j0; }
                v = fmaf(-2.f, acc[mf][nf][3], sb[nf].y);
                if (j1 != ig + 8 && v < mn[mf * 2 + 1]) { mn[mf * 2 + 1] = v; mi[mf * 2 + 1] = j1; }
            }
        }

        // ---- fused zero-fill: 32x256 tile, fully coalesced ----
        {
            const float4 z4 = make_float4(0.f, 0.f, 0.f, 0.f);
            float4* p = (float4*)(out + (size_t)(row0 + (tid >> 4)) * NPTS + cb) + (tid & 15);
            #pragma unroll
            for (int i = 0; i < 4; i++) p[i * 16] = z4;
        }
    }

    // ---- intra-warp (lt) reduce via packed-u64 shfl min, then cross-warp ----
    #pragma unroll
    for (int q = 0; q < 4; q++) {
        uint32_t b = __float_as_uint(mn[q]);
        b ^= (uint32_t)(((int32_t)b >> 31)) | 0x80000000u;   // monotonic map
        unsigned long long k = ((unsigned long long)b << 32) | (unsigned)mi[q];
        unsigned long long o;
        o = __shfl_xor_sync(0xffffffffu, k, 1); if (o < k) k = o;
        o = __shfl_xor_sync(0xffffffffu, k, 2); if (o < k) k = o;
        if (lt == 0) skey[(q >> 1) * 16 + (q & 1) * 8 + lg][cg] = k;
    }
    __syncthreads();
    if (tid < MB) {
        unsigned long long k = skey[tid][0];
        #pragma unroll
        for (int x = 1; x < 16; x++) {
            unsigned long long o = skey[tid][x];
            if (o < k) k = o;
        }
        atomicMin(&g_key[row0 + tid], k);
    }
}

extern "C" void kernel_launch(void* const* d_in, const int* in_sizes, int n_in,
                              void* d_out, int out_size) {
    const float* X = (const float*)d_in[0];
    float* out = (float*)d_out;
    sq_kernel<<<NPTS / 8, 256>>>(X);
    prep_b<<<1024, 256>>>(X);
    init_kernel<<<NPTS / 256, 256>>>();
    knn_kernel<<<dim3(NPTS / MB, NCHUNK), NT>>>(out);
    final_kernel<<<NPTS / 256, 256>>>(out);
}

// round 16
// speedup vs baseline: 1.0760x; 1.0760x over previous
#include <cuda_runtime.h>
#include <cuda_fp16.h>
#include <cstdint>

#define NPTS 16384
#define DIM  64
#define MB   32                  // rows per CTA
#define NBT  256                 // cols per tile
#define NT   512                 // threads (16 warps)
#define NTILES (NPTS / NBT)      // 64 col tiles total

__device__ float g_sq[NPTS];
__device__ unsigned long long g_key[NPTS];
__device__ uint4 g_bf4[262144];          // 4MB fragment-major fp16 2-plane X (A and B)

// ---------------- helpers ----------------
#define MMA16(c, a0, a1, a2, a3, b0, b1) \
    asm volatile("mma.sync.aligned.m16n8k16.row.col.f32.f16.f16.f32 " \
        "{%0,%1,%2,%3},{%4,%5,%6,%7},{%8,%9},{%0,%1,%2,%3};" \
        : "+f"((c)[0]), "+f"((c)[1]), "+f"((c)[2]), "+f"((c)[3]) \
        : "r"(a0), "r"(a1), "r"(a2), "r"(a3), "r"(b0), "r"(b1))

__device__ __forceinline__ uint32_t pack_plane(float2 v, int p) {
    __half h0x = __float2half_rn(v.x);
    __half h0y = __float2half_rn(v.y);
    __half lx, ly;
    if (p == 0) { lx = h0x; ly = h0y; }
    else {
        lx = __float2half_rn(v.x - __half2float(h0x));
        ly = __float2half_rn(v.y - __half2float(h0y));
    }
    return (uint32_t)__half_as_ushort(lx) | ((uint32_t)__half_as_ushort(ly) << 16);
}

__device__ __forceinline__ unsigned long long mkkey(float v, int idx) {
    uint32_t b = __float_as_uint(v);
    b ^= (uint32_t)(((int32_t)b >> 31)) | 0x80000000u;   // monotonic map
    return ((unsigned long long)b << 32) | (unsigned)idx;
}

// ---------------- small kernels ----------------
__global__ void sq_kernel(const float* __restrict__ X) {
    int warp = (blockIdx.x * blockDim.x + threadIdx.x) >> 5;
    int lane = threadIdx.x & 31;
    if (warp >= NPTS) return;
    const float* row = X + (size_t)warp * DIM;
    float a = row[lane], b = row[lane + 32];
    float s = a * a + b * b;
    #pragma unroll
    for (int o = 16; o; o >>= 1) s += __shfl_xor_sync(0xffffffffu, s, o);
    if (lane == 0) g_sq[warp] = s;
}

// fragment-major fp16 planes: uint4 index = (((tile*4+s)*2+p)*8+npair)*32+lane
__global__ void prep_b(const float* __restrict__ X) {
    int gid = blockIdx.x * blockDim.x + threadIdx.x;   // 0..262143
    int lane = gid & 31;
    int r1 = gid >> 5;
    int npair = r1 & 7;
    int r2 = r1 >> 3;
    int p = r2 & 1;
    int r3 = r2 >> 1;
    int s = r3 & 3;
    int tile = r3 >> 2;
    int lg = lane >> 2, lt = lane & 3;
    int j0 = tile * 128 + npair * 16 + lg;
    int j1 = j0 + 8;
    int kb = s * 16 + 2 * lt;
    float2 e00 = *(const float2*)(X + (size_t)j0 * DIM + kb);
    float2 e01 = *(const float2*)(X + (size_t)j0 * DIM + kb + 8);
    float2 e10 = *(const float2*)(X + (size_t)j1 * DIM + kb);
    float2 e11 = *(const float2*)(X + (size_t)j1 * DIM + kb + 8);
    uint4 o;
    o.x = pack_plane(e00, p);
    o.y = pack_plane(e01, p);
    o.z = pack_plane(e10, p);
    o.w = pack_plane(e11, p);
    g_bf4[gid] = o;
}

__global__ void init_kernel() {
    g_key[blockIdx.x * blockDim.x + threadIdx.x] = 0xFFFFFFFFFFFFFFFFull;
}

__global__ void final_kernel(float* __restrict__ out) {
    int row = blockIdx.x * blockDim.x + threadIdx.x;
    unsigned idx = (unsigned)(g_key[row] & 0xFFFFFFFFu);
    out[(size_t)row * NPTS + row] = 1.0f;
    out[(size_t)row * NPTS + idx] = 1.0f;
}

// ---------------- main kernel: symmetric upper-triangle sweep ----------------
__global__ void __launch_bounds__(NT, 1)
knn_kernel(float* __restrict__ out) {
    __shared__ unsigned long long skey[MB][8];

    const int tid  = threadIdx.x;
    const int lane = tid & 31;
    const int wid  = tid >> 5;
    const int wm   = wid >> 3;          // 0..1 -> rows wm*16
    const int cg   = wid & 7;           // 0..7 -> cols cg*32
    const int lg   = lane >> 2;         // 0..7
    const int lt   = lane & 3;          // 0..3
    const int row0 = blockIdx.x * MB;
    const int ct0  = blockIdx.x >> 3;   // first col tile: align_down(row0,256)/256

    // ---- A fragments: resident in registers ----
    uint4 a[2][4];                       // [plane][stage]
    {
        const int rbA = blockIdx.x * 2 + wm;
        const int tA = rbA >> 3, npA = rbA & 7;
        #pragma unroll
        for (int s = 0; s < 4; s++)
            #pragma unroll
            for (int p = 0; p < 2; p++)
                a[p][s] = g_bf4[((((tA * 4 + s) * 2) + p) * 8 + npA) * 32 + lane];
    }

    // row norms for this warp's rows (for col-side keys)
    const float saA = g_sq[row0 + wm * 16 + lg];
    const float saB = g_sq[row0 + wm * 16 + lg + 8];

    // B base pointer (immediate offsets inside tile)
    const uint4* bp = g_bf4
        + (size_t)(ct0 * 2 + (cg >> 2)) * 2048
        + (cg & 3) * 64 + lane;

    float mn[2];
    int   mi[2];
    mn[0] = mn[1] = 3.402823466e38f;
    mi[0] = mi[1] = 0;

    // prologue: prefetch stages 0,1 of first tile
    uint4 Bb[2][2][2];                   // [buf][plane][pp]
    #pragma unroll
    for (int p = 0; p < 2; p++)
        #pragma unroll
        for (int pp = 0; pp < 2; pp++) {
            Bb[0][p][pp] = bp[0 * 512 + p * 256 + pp * 32];
            Bb[1][p][pp] = bp[1 * 512 + p * 256 + pp * 32];
        }

    for (int ct = ct0; ct < NTILES; ct++) {
        const int cb = ct * NBT;

        // prefetch sq-norms for this tile's cols
        float2 sb[4];
        #pragma unroll
        for (int nf = 0; nf < 4; nf++)
            sb[nf] = __ldg((const float2*)&g_sq[cb + cg * 32 + nf * 8 + 2 * lt]);

        float acc[4][4];
        #pragma unroll
        for (int nf = 0; nf < 4; nf++)
            #pragma unroll
            for (int r = 0; r < 4; r++) acc[nf][r] = 0.f;

        #pragma unroll
        for (int s = 0; s < 4; s++) {
            const int cur = s & 1;
            #pragma unroll
            for (int nf = 0; nf < 4; nf++) {
                const uint4& B = Bb[cur][0][nf >> 1];
                MMA16(acc[nf], a[0][s].x, a[0][s].z, a[0][s].y, a[0][s].w,
                      (nf & 1) ? B.z : B.x, (nf & 1) ? B.w : B.y);
            }
            #pragma unroll
            for (int nf = 0; nf < 4; nf++) {
                const uint4& B = Bb[cur][1][nf >> 1];
                MMA16(acc[nf], a[0][s].x, a[0][s].z, a[0][s].y, a[0][s].w,
                      (nf & 1) ? B.z : B.x, (nf & 1) ? B.w : B.y);
            }
            #pragma unroll
            for (int nf = 0; nf < 4; nf++) {
                const uint4& B = Bb[cur][0][nf >> 1];
                MMA16(acc[nf], a[1][s].x, a[1][s].z, a[1][s].y, a[1][s].w,
                      (nf & 1) ? B.z : B.x, (nf & 1) ? B.w : B.y);
            }
            // depth-2 WAR-ring prefetch
            if (s < 2) {
                #pragma unroll
                for (int p = 0; p < 2; p++)
                    #pragma unroll
                    for (int pp = 0; pp < 2; pp++)
                        Bb[cur][p][pp] = bp[(s + 2) * 512 + p * 256 + pp * 32];
            } else if (ct + 1 < NTILES) {
                #pragma unroll
                for (int p = 0; p < 2; p++)
                    #pragma unroll
                    for (int pp = 0; pp < 2; pp++)
                        Bb[cur][p][pp] = bp[4096 + (s - 2) * 512 + p * 256 + pp * 32];
            }
        }
        bp += 4096;

        // ---- row-side argmin: key (sb - 2*dot), self excluded ----
        {
            const int ig = row0 + wm * 16 + lg;
            #pragma unroll
            for (int nf = 0; nf < 4; nf++) {
                const int lc = cg * 32 + nf * 8 + 2 * lt;
                const int j0 = cb + lc, j1 = j0 + 1;
                float v;
                v = fmaf(-2.f, acc[nf][0], sb[nf].x);
                if (j0 != ig && v < mn[0]) { mn[0] = v; mi[0] = j0; }
                v = fmaf(-2.f, acc[nf][1], sb[nf].y);
                if (j1 != ig && v < mn[0]) { mn[0] = v; mi[0] = j1; }
                v = fmaf(-2.f, acc[nf][2], sb[nf].x);
                if (j0 != ig + 8 && v < mn[1]) { mn[1] = v; mi[1] = j0; }
                v = fmaf(-2.f, acc[nf][3], sb[nf].y);
                if (j1 != ig + 8 && v < mn[1]) { mn[1] = v; mi[1] = j1; }
            }
        }

        // ---- col-side argmin: key (sa - 2*dot) over this warp's 16 rows ----
        {
            const int rgA = row0 + wm * 16 + lg;
            const int rgB = rgA + 8;
            #pragma unroll
            for (int nf = 0; nf < 4; nf++) {
                const int lc = cg * 32 + nf * 8 + 2 * lt;
                const int j0 = cb + lc, j1 = j0 + 1;
                float v0a = (rgA == j0) ? 3.402823466e38f : fmaf(-2.f, acc[nf][0], saA);
                float v0b = (rgB == j0) ? 3.402823466e38f : fmaf(-2.f, acc[nf][2], saB);
                float v1a = (rgA == j1) ? 3.402823466e38f : fmaf(-2.f, acc[nf][1], saA);
                float v1b = (rgB == j1) ? 3.402823466e38f : fmaf(-2.f, acc[nf][3], saB);
                unsigned long long k0 = mkkey(v0a, rgA);
                unsigned long long t0 = mkkey(v0b, rgB);
                if (t0 < k0) k0 = t0;
                unsigned long long k1 = mkkey(v1a, rgA);
                unsigned long long t1 = mkkey(v1b, rgB);
                if (t1 < k1) k1 = t1;
                #pragma unroll
                for (int off = 4; off <= 16; off <<= 1) {
                    unsigned long long o0 = __shfl_xor_sync(0xffffffffu, k0, off);
                    if (o0 < k0) k0 = o0;
                    unsigned long long o1 = __shfl_xor_sync(0xffffffffu, k1, off);
                    if (o1 < k1) k1 = o1;
                }
                if (lg == 0) {
                    atomicMin(&g_key[j0], k0);
                    atomicMin(&g_key[j1], k1);
                }
            }
        }

        // ---- zero-fill main 32x256 tile + mirrored 256x32 tile ----
        {
            const float4 z4 = make_float4(0.f, 0.f, 0.f, 0.f);
            float4* p = (float4*)(out + (size_t)(row0 + (tid >> 4)) * NPTS + cb) + (tid & 15);
            #pragma unroll
            for (int i = 0; i < 4; i++) p[i * 16] = z4;
            // mirror: 256 rows x 32 cols = 2048 float4 (8 per row)
            #pragma unroll
            for (int i = 0; i < 4; i++) {
                int g = i * NT + tid;
                int mr = g >> 3, q = g & 7;
                *(float4*)(out + (size_t)(cb + mr) * NPTS + row0 + q * 4) = z4;
            }
        }
    }

    // ---- row-side cross-warp reduction, then atomicMin merge ----
    #pragma unroll
    for (int h = 0; h < 2; h++) {
        unsigned long long k = mkkey(mn[h], mi[h]);
        unsigned long long o;
        o = __shfl_xor_sync(0xffffffffu, k, 1); if (o < k) k = o;
        o = __shfl_xor_sync(0xffffffffu, k, 2); if (o < k) k = o;
        if (lt == 0) skey[wm * 16 + h * 8 + lg][cg] = k;
    }
    __syncthreads();
    if (tid < MB) {
        unsigned long long k = skey[tid][0];
        #pragma unroll
        for (int x = 1; x < 8; x++) {
            unsigned long long o = skey[tid][x];
            if (o < k) k = o;
        }
        atomicMin(&g_key[row0 + tid], k);
    }
}

extern "C" void kernel_launch(void* const* d_in, const int* in_sizes, int n_in,
                              void* d_out, int out_size) {
    const float* X = (const float*)d_in[0];
    float* out = (float*)d_out;
    sq_kernel<<<NPTS / 8, 256>>>(X);
    prep_b<<<1024, 256>>>(X);
    init_kernel<<<NPTS / 256, 256>>>();
    knn_kernel<<<NPTS / MB, NT>>>(out);
    final_kernel<<<NPTS / 256, 256>>>(out);
}